// round 6
// baseline (speedup 1.0000x reference)
#include <cuda_runtime.h>
#include <math.h>

#define NN 50000
#define NE 800000
#define F  128
#define AP 68   // padded row stride (uints) for bf16x2 smem tiles: conflict-free fragments

// ---- zeroed-by-memset scratch block (single memset covers all of it) ----
#define OFF_DEGOUT 0
#define OFF_DEGIN  NN
#define OFF_SVAL   (2 * NN)          // 64 scan partial values
#define OFF_SFLAG  (2 * NN + 64)     // 64 ready flags
#define OFF_TCTR   (2 * NN + 128)    // 8 dynamic-tile counters
#define PRE_INTS   (2 * NN + 160)
__device__ int g_pre[PRE_INTS];

__device__ __align__(16) float g_srcnorm[NN];
__device__ __align__(16) float g_dstnorm[NN];
__device__ int   g_offsets[NN + 1];
__device__ int   g_cursor[NN];
__device__ int   g_csrsrc[NE];
// bf16-packed feature buffers (2 vals per uint)
__device__ __align__(16) unsigned g_h0[(size_t)NN * F / 2];
__device__ __align__(16) unsigned g_h1[(size_t)NN * F / 2];
__device__ __align__(16) unsigned g_hy[(size_t)NN * 64 / 2];

// ---------------- helpers ----------------
__device__ __forceinline__ unsigned pack_bf2(float lo, float hi) {
    unsigned r;
    asm("cvt.rn.bf16x2.f32 %0, %1, %2;" : "=r"(r) : "f"(hi), "f"(lo));
    return r;
}
#define BF_LO(u) __uint_as_float((u) << 16)
#define BF_HI(u) __uint_as_float((u) & 0xffff0000u)

__device__ __forceinline__ void mma_bf16(
    float& c0, float& c1, float& c2, float& c3,
    unsigned a0, unsigned a1, unsigned a2, unsigned a3,
    unsigned b0, unsigned b1)
{
    asm("mma.sync.aligned.m16n8k16.row.col.f32.bf16.bf16.f32 "
        "{%0,%1,%2,%3},{%4,%5,%6,%7},{%8,%9},{%0,%1,%2,%3};"
        : "+f"(c0), "+f"(c1), "+f"(c2), "+f"(c3)
        : "r"(a0), "r"(a1), "r"(a2), "r"(a3), "r"(b0), "r"(b1));
}

__device__ __forceinline__ int warp_incl_scan(int s, int lane) {
    #pragma unroll
    for (int o = 1; o < 32; o <<= 1) {
        int t = __shfl_up_sync(0xffffffffu, s, o);
        if (lane >= o) s += t;
    }
    return s;
}

// ---------------- preprocessing ----------------
__global__ void k_deg(const int* __restrict__ src, const int* __restrict__ dst, int e) {
    int i = blockIdx.x * blockDim.x + threadIdx.x;
    if (i < e) {
        atomicAdd(&g_pre[OFF_DEGOUT + src[i]], 1);
        atomicAdd(&g_pre[OFF_DEGIN + dst[i]], 1);
    }
}

// single-pass scan (decoupled lookback, 49 co-resident blocks) + norms + cursor
__global__ void __launch_bounds__(1024) k_scanall(int n, int e) {
    __shared__ int warpsum[32];
    __shared__ int blockbase;
    int b = blockIdx.x;
    int tid = threadIdx.x;
    int lane = tid & 31, wid = tid >> 5;
    int i = b * 1024 + tid;

    int v = (i < n) ? g_pre[OFF_DEGIN + i] : 0;
    int s = warp_incl_scan(v, lane);
    if (lane == 31) warpsum[wid] = s;
    __syncthreads();
    if (wid == 0) warpsum[lane] = warp_incl_scan(warpsum[lane], lane);
    __syncthreads();
    int incl = s + (wid > 0 ? warpsum[wid - 1] : 0);

    if (tid == 0) {
        int total = warpsum[31];
        int prev = 0;
        if (b > 0) {
            volatile int* fl = (volatile int*)&g_pre[OFF_SFLAG + b - 1];
            while (*fl == 0) { }
            __threadfence();
            prev = *((volatile int*)&g_pre[OFF_SVAL + b - 1]);
        }
        *((volatile int*)&g_pre[OFF_SVAL + b]) = prev + total;
        __threadfence();
        *((volatile int*)&g_pre[OFF_SFLAG + b]) = 1;
        blockbase = prev;
    }
    __syncthreads();

    if (i < n) {
        int o = blockbase + incl - v;
        g_offsets[i] = o;
        g_cursor[i] = o;
        int od = g_pre[OFF_DEGOUT + i];
        int id = v;
        g_srcnorm[i] = od > 0 ? rsqrtf((float)od) : 0.f;
        g_dstnorm[i] = id > 0 ? rsqrtf((float)id) : 0.f;
    }
    if (b == 0 && tid == 0) g_offsets[n] = e;
}

// fused: CSR scatter (blocks [0, eb)) + h0 = bf16(features * src_norm) (blocks [eb, ...))
__global__ void k_scatter_scale(
    const int* __restrict__ src, const int* __restrict__ dst,
    const float* __restrict__ feats, int e, int n, int eb)
{
    int b = blockIdx.x;
    if (b < eb) {
        int i = b * 256 + threadIdx.x;
        if (i < e) {
            int d = dst[i];
            int pos = atomicAdd(&g_cursor[d], 1);
            g_csrsrc[pos] = src[i];
        }
    } else {
        int i = (b - eb) * 256 + threadIdx.x;   // over n * (F/4)
        if (i < n * (F / 4)) {
            int row = i >> 5;
            float4 v = ((const float4*)feats)[i];
            float s = g_srcnorm[row];
            uint2 o;
            o.x = pack_bf2(v.x * s, v.y * s);
            o.y = pack_bf2(v.z * s, v.w * s);
            ((uint2*)g_h0)[i] = o;
        }
    }
}

// ---------------- fused conv layer: gather-SpMM + bf16 MMA + relu + src_norm fold ----
// dynamic tile scheduling (gmem atomic) + in-block node stealing (smem atomic)
__global__ void __launch_bounds__(256, 5) k_layer128(
    const unsigned* __restrict__ xs,      // bf16-packed, row stride F/2 uints
    const float* __restrict__ W,          // [F][F] row-major fp32
    const float* __restrict__ bias,
    unsigned* __restrict__ out,           // bf16-packed output
    int n, int numTiles, int slot)
{
    __shared__ unsigned shWb[F * AP];     // 34816 B
    __shared__ unsigned shAb[16 * AP];    // 4352 B
    __shared__ float    shB[F];
    __shared__ int      sh_t, sh_ctr;

    int tid = threadIdx.x;
    for (int i = tid; i < F * (F / 2); i += 256) {
        int k2 = i >> 7, nn = i & (F - 1);
        shWb[nn * AP + k2] = pack_bf2(W[(2 * k2) * F + nn], W[(2 * k2 + 1) * F + nn]);
    }
    if (tid < F / 4) ((float4*)shB)[tid] = ((const float4*)bias)[tid];

    int w = tid >> 5, lane = tid & 31;
    int g = lane >> 2, tig = lane & 3;

    while (true) {
        if (tid == 0) {
            sh_t = atomicAdd(&g_pre[OFF_TCTR + slot], 1);
            sh_ctr = 0;
        }
        __syncthreads();
        int t = sh_t;
        if (t >= numTiles) break;
        int base = t * 16;

        // --- aggregation with node stealing: warp pops next local node ---
        for (;;) {
            int k;
            if (lane == 0) k = atomicAdd(&sh_ctr, 1);
            k = __shfl_sync(0xffffffffu, k, 0);
            if (k >= 16) break;
            int m = base + k;
            float4 acc = make_float4(0.f, 0.f, 0.f, 0.f);
            if (m < n) {
                int e = g_offsets[m], end = g_offsets[m + 1];
                const unsigned* xb = xs + lane * 2;
                for (; e + 8 <= end; e += 8) {
                    uint2 u[8];
                    #pragma unroll
                    for (int q = 0; q < 8; q++) {
                        int idx = g_csrsrc[e + q];
                        u[q] = *(const uint2*)(xb + (size_t)idx * (F / 2));
                    }
                    #pragma unroll
                    for (int q = 0; q < 8; q++) {
                        acc.x += BF_LO(u[q].x); acc.y += BF_HI(u[q].x);
                        acc.z += BF_LO(u[q].y); acc.w += BF_HI(u[q].y);
                    }
                }
                for (; e + 4 <= end; e += 4) {
                    uint2 u[4];
                    #pragma unroll
                    for (int q = 0; q < 4; q++) {
                        int idx = g_csrsrc[e + q];
                        u[q] = *(const uint2*)(xb + (size_t)idx * (F / 2));
                    }
                    #pragma unroll
                    for (int q = 0; q < 4; q++) {
                        acc.x += BF_LO(u[q].x); acc.y += BF_HI(u[q].x);
                        acc.z += BF_LO(u[q].y); acc.w += BF_HI(u[q].y);
                    }
                }
                for (; e < end; e++) {
                    uint2 u0 = *(const uint2*)(xb + (size_t)g_csrsrc[e] * (F / 2));
                    acc.x += BF_LO(u0.x); acc.y += BF_HI(u0.x);
                    acc.z += BF_LO(u0.y); acc.w += BF_HI(u0.y);
                }
                float dn = g_dstnorm[m];
                acc.x *= dn; acc.y *= dn; acc.z *= dn; acc.w *= dn;
            }
            shAb[k * AP + lane * 2]     = pack_bf2(acc.x, acc.y);
            shAb[k * AP + lane * 2 + 1] = pack_bf2(acc.z, acc.w);
        }
        __syncthreads();

        // --- GEMM: warp w owns cols [16w, 16w+16) ---
        int nb0 = w * 16, nb1 = nb0 + 8;
        float2 bb0 = *(float2*)(shB + nb0 + 2 * tig);
        float2 bb1 = *(float2*)(shB + nb1 + 2 * tig);
        float c00 = bb0.x, c01 = bb0.y, c02 = bb0.x, c03 = bb0.y;
        float c10 = bb1.x, c11 = bb1.y, c12 = bb1.x, c13 = bb1.y;

        const unsigned* A0 = shAb + g * AP;
        const unsigned* A1 = shAb + (g + 8) * AP;
        const unsigned* B0 = shWb + (nb0 + g) * AP;
        const unsigned* B1 = shWb + (nb1 + g) * AP;
        #pragma unroll
        for (int kt = 0; kt < 8; kt++) {
            int j0 = kt * 8;
            unsigned a0 = A0[j0 + tig],     a1 = A1[j0 + tig];
            unsigned a2 = A0[j0 + 4 + tig], a3 = A1[j0 + 4 + tig];
            mma_bf16(c00, c01, c02, c03, a0, a1, a2, a3, B0[j0 + tig], B0[j0 + 4 + tig]);
            mma_bf16(c10, c11, c12, c13, a0, a1, a2, a3, B1[j0 + tig], B1[j0 + 4 + tig]);
        }

        int m0 = base + g, m1 = base + g + 8;
        if (m0 < n) {
            float sn = g_srcnorm[m0];
            unsigned* o = out + (size_t)m0 * (F / 2);
            o[nb0 / 2 + tig] = pack_bf2(fmaxf(c00, 0.f) * sn, fmaxf(c01, 0.f) * sn);
            o[nb1 / 2 + tig] = pack_bf2(fmaxf(c10, 0.f) * sn, fmaxf(c11, 0.f) * sn);
        }
        if (m1 < n) {
            float sn = g_srcnorm[m1];
            unsigned* o = out + (size_t)m1 * (F / 2);
            o[nb0 / 2 + tig] = pack_bf2(fmaxf(c02, 0.f) * sn, fmaxf(c03, 0.f) * sn);
            o[nb1 / 2 + tig] = pack_bf2(fmaxf(c12, 0.f) * sn, fmaxf(c13, 0.f) * sn);
        }
        __syncthreads();
    }
}

// ---------------- y = x2s @ W3 via bf16 MMA (dynamic tiles) ----------------
__global__ void __launch_bounds__(256) k_pre3(
    const unsigned* __restrict__ x,       // bf16-packed, row stride 64 uints
    const float* __restrict__ W3,         // [F][64] row-major fp32
    unsigned* __restrict__ y, int n, int numTiles, int slot)
{
    __shared__ unsigned shWb[64 * AP];
    __shared__ unsigned shXb[16 * AP];
    __shared__ int sh_t;
    int tid = threadIdx.x;
    for (int i = tid; i < 64 * (F / 2); i += 256) {
        int k2 = i >> 6, nn = i & 63;
        shWb[nn * AP + k2] = pack_bf2(W3[(2 * k2) * 64 + nn], W3[(2 * k2 + 1) * 64 + nn]);
    }

    int w = tid >> 5, lane = tid & 31;
    int g = lane >> 2, tig = lane & 3;

    while (true) {
        if (tid == 0) sh_t = atomicAdd(&g_pre[OFF_TCTR + slot], 1);
        __syncthreads();
        int t = sh_t;
        if (t >= numTiles) break;
        int base = t * 16;
        {
            int r = tid >> 4, q = tid & 15;
            int node = base + r;
            uint4 v = (node < n) ? ((const uint4*)(x + (size_t)node * 64))[q]
                                 : make_uint4(0u, 0u, 0u, 0u);
            unsigned* p = shXb + r * AP + q * 4;
            p[0] = v.x; p[1] = v.y; p[2] = v.z; p[3] = v.w;
        }
        __syncthreads();

        int nb = w * 8;
        float c0 = 0.f, c1 = 0.f, c2 = 0.f, c3 = 0.f;
        const unsigned* A0 = shXb + g * AP;
        const unsigned* A1 = shXb + (g + 8) * AP;
        const unsigned* B0 = shWb + (nb + g) * AP;
        #pragma unroll
        for (int kt = 0; kt < 8; kt++) {
            int j0 = kt * 8;
            mma_bf16(c0, c1, c2, c3,
                     A0[j0 + tig], A1[j0 + tig], A0[j0 + 4 + tig], A1[j0 + 4 + tig],
                     B0[j0 + tig], B0[j0 + 4 + tig]);
        }
        int m0 = base + g, m1 = base + g + 8;
        if (m0 < n) y[(size_t)m0 * 32 + nb / 2 + tig] = pack_bf2(c0, c1);
        if (m1 < n) y[(size_t)m1 * 32 + nb / 2 + tig] = pack_bf2(c2, c3);
        __syncthreads();
    }
}

// ---------------- layer 3 aggregation (bf16, width 64) + bias + relu + head + sigmoid ------
__global__ void k_layer3(
    const unsigned* __restrict__ y, const float* __restrict__ b3,
    const float* __restrict__ Wp, const float* __restrict__ bp,
    float* __restrict__ out, int n)
{
    int gw = (blockIdx.x * blockDim.x + threadIdx.x) >> 5;
    int lane = threadIdx.x & 31;
    if (gw >= n) return;
    int m = gw;
    int e = g_offsets[m], end = g_offsets[m + 1];
    float2 acc = make_float2(0.f, 0.f);
    const unsigned* yb = y + lane;
    for (; e + 8 <= end; e += 8) {
        unsigned u[8];
        #pragma unroll
        for (int q = 0; q < 8; q++) u[q] = yb[(size_t)g_csrsrc[e + q] * 32];
        #pragma unroll
        for (int q = 0; q < 8; q++) { acc.x += BF_LO(u[q]); acc.y += BF_HI(u[q]); }
    }
    for (; e + 4 <= end; e += 4) {
        unsigned u[4];
        #pragma unroll
        for (int q = 0; q < 4; q++) u[q] = yb[(size_t)g_csrsrc[e + q] * 32];
        #pragma unroll
        for (int q = 0; q < 4; q++) { acc.x += BF_LO(u[q]); acc.y += BF_HI(u[q]); }
    }
    for (; e < end; e++) {
        unsigned u0 = yb[(size_t)g_csrsrc[e] * 32];
        acc.x += BF_LO(u0); acc.y += BF_HI(u0);
    }
    float dn = g_dstnorm[m];
    float2 bb = *(const float2*)(b3 + lane * 2);
    float hx = fmaxf(acc.x * dn + bb.x, 0.f);
    float hy = fmaxf(acc.y * dn + bb.y, 0.f);
    float2 wp = *(const float2*)(Wp + lane * 2);
    float p = hx * wp.x + hy * wp.y;
    #pragma unroll
    for (int o = 16; o; o >>= 1) p += __shfl_xor_sync(0xffffffffu, p, o);
    if (lane == 0) {
        float l = p + bp[0];
        out[m] = 1.f / (1.f + __expf(-l));
    }
}

// ---------------- launch ----------------
extern "C" void kernel_launch(void* const* d_in, const int* in_sizes, int n_in,
                              void* d_out, int out_size)
{
    const float* feats = (const float*)d_in[0];
    const int*   src   = (const int*)d_in[1];
    const int*   dst   = (const int*)d_in[2];
    // d_in[3] = edge_types (unused)
    const float* W1 = (const float*)d_in[4];
    const float* b1 = (const float*)d_in[5];
    const float* W2 = (const float*)d_in[6];
    const float* b2 = (const float*)d_in[7];
    const float* W3 = (const float*)d_in[8];
    const float* b3 = (const float*)d_in[9];
    const float* Wp = (const float*)d_in[10];
    const float* bp = (const float*)d_in[11];
    float* out = (float*)d_out;

    int n = in_sizes[0] / F;   // 50000
    int e = in_sizes[1];       // 800000

    unsigned *h0, *h1, *hy;
    int* prep;
    cudaGetSymbolAddress((void**)&h0, g_h0);
    cudaGetSymbolAddress((void**)&h1, g_h1);
    cudaGetSymbolAddress((void**)&hy, g_hy);
    cudaGetSymbolAddress((void**)&prep, g_pre);

    int nb = (n + 1023) / 1024;               // 49 scan blocks
    int tiles = (n + 15) / 16;
    int eb = (e + 255) / 256;
    int sb = (n * (F / 4) + 255) / 256;

    cudaMemsetAsync(prep, 0, sizeof(int) * PRE_INTS);
    k_deg          <<<(e + 255) / 256, 256>>>(src, dst, e);
    k_scanall      <<<nb, 1024>>>(n, e);
    k_scatter_scale<<<eb + sb, 256>>>(src, dst, feats, e, n, eb);

    k_layer128<<<740, 256>>>(h0, W1, b1, h1, n, tiles, 0);
    k_layer128<<<740, 256>>>(h1, W2, b2, h0, n, tiles, 1);
    k_pre3    <<<1184, 256>>>(h0, W3, hy, n, tiles, 2);
    k_layer3  <<<(n * 32 + 255) / 256, 256>>>(hy, b3, Wp, bp, out, n);
}

// round 7
// speedup vs baseline: 1.4006x; 1.4006x over previous
#include <cuda_runtime.h>
#include <math.h>

#define NN 50000
#define NE 800000
#define F  128
#define AP 68   // padded row stride (uints) for bf16x2 smem tiles: conflict-free fragments

// ---- zeroed-by-memset scratch block (single memset covers all of it) ----
#define OFF_DEGOUT 0
#define OFF_DEGIN  NN
#define OFF_TCTR   (2 * NN)          // 8 dynamic-tile counters
#define PRE_INTS   (2 * NN + 8)
__device__ int g_pre[PRE_INTS];

__device__ __align__(16) float g_srcnorm[NN];
__device__ __align__(16) float g_dstnorm[NN];
__device__ int   g_offsets[NN + 1];
__device__ int   g_cursor[NN];
__device__ int   g_csrsrc[NE];
__device__ int   g_blksums[64];
__device__ int   g_blkoffs[64];
// bf16-packed feature buffers (2 vals per uint)
__device__ __align__(16) unsigned g_h0[(size_t)NN * F / 2];
__device__ __align__(16) unsigned g_h1[(size_t)NN * F / 2];
__device__ __align__(16) unsigned g_hy[(size_t)NN * 64 / 2];

// ---------------- helpers ----------------
__device__ __forceinline__ unsigned pack_bf2(float lo, float hi) {
    unsigned r;
    asm("cvt.rn.bf16x2.f32 %0, %1, %2;" : "=r"(r) : "f"(hi), "f"(lo));
    return r;
}
#define BF_LO(u) __uint_as_float((u) << 16)
#define BF_HI(u) __uint_as_float((u) & 0xffff0000u)

__device__ __forceinline__ void mma_bf16(
    float& c0, float& c1, float& c2, float& c3,
    unsigned a0, unsigned a1, unsigned a2, unsigned a3,
    unsigned b0, unsigned b1)
{
    asm("mma.sync.aligned.m16n8k16.row.col.f32.bf16.bf16.f32 "
        "{%0,%1,%2,%3},{%4,%5,%6,%7},{%8,%9},{%0,%1,%2,%3};"
        : "+f"(c0), "+f"(c1), "+f"(c2), "+f"(c3)
        : "r"(a0), "r"(a1), "r"(a2), "r"(a3), "r"(b0), "r"(b1));
}

__device__ __forceinline__ int warp_incl_scan(int s, int lane) {
    #pragma unroll
    for (int o = 1; o < 32; o <<= 1) {
        int t = __shfl_up_sync(0xffffffffu, s, o);
        if (lane >= o) s += t;
    }
    return s;
}

// ---------------- preprocessing ----------------
__global__ void k_deg(const int* __restrict__ src, const int* __restrict__ dst, int e) {
    int i = blockIdx.x * blockDim.x + threadIdx.x;
    if (i < e) {
        atomicAdd(&g_pre[OFF_DEGOUT + src[i]], 1);
        atomicAdd(&g_pre[OFF_DEGIN + dst[i]], 1);
    }
}

// per-1024-block exclusive scan of indeg via warp shuffles
__global__ void k_scan1(int n) {
    __shared__ int warpsum[32];
    int tid = threadIdx.x;
    int i = blockIdx.x * 1024 + tid;
    int lane = tid & 31, wid = tid >> 5;
    int v = (i < n) ? g_pre[OFF_DEGIN + i] : 0;
    int s = warp_incl_scan(v, lane);
    if (lane == 31) warpsum[wid] = s;
    __syncthreads();
    if (wid == 0) warpsum[lane] = warp_incl_scan(warpsum[lane], lane);
    __syncthreads();
    int incl = s + (wid > 0 ? warpsum[wid - 1] : 0);
    if (i < n) g_offsets[i] = incl - v;
    if (tid == 1023) g_blksums[blockIdx.x] = incl;
}

// 1-warp scan over block sums (nb <= 64)
__global__ void k_scan2(int nb) {
    int lane = threadIdx.x;
    int acc = 0;
    for (int b = 0; b < nb; b += 32) {
        int v = (b + lane < nb) ? g_blksums[b + lane] : 0;
        int s = warp_incl_scan(v, lane);
        if (b + lane < nb) g_blkoffs[b + lane] = acc + s - v;
        acc += __shfl_sync(0xffffffffu, s, 31);
    }
}

// finish scan + compute norms (fused)
__global__ void k_scan3(int n, int e) {
    int i = blockIdx.x * blockDim.x + threadIdx.x;
    if (i < n) {
        int o = g_offsets[i] + g_blkoffs[i >> 10];
        g_offsets[i] = o;
        g_cursor[i] = o;
        int od = g_pre[OFF_DEGOUT + i];
        int id = g_pre[OFF_DEGIN + i];
        g_srcnorm[i] = od > 0 ? rsqrtf((float)od) : 0.f;
        g_dstnorm[i] = id > 0 ? rsqrtf((float)id) : 0.f;
    }
    if (i == 0) g_offsets[n] = e;
}

// fused: CSR scatter (blocks [0, eb)) + h0 = bf16(features * src_norm) (blocks [eb, ...))
__global__ void k_scatter_scale(
    const int* __restrict__ src, const int* __restrict__ dst,
    const float* __restrict__ feats, int e, int n, int eb)
{
    int b = blockIdx.x;
    if (b < eb) {
        int i = b * 256 + threadIdx.x;
        if (i < e) {
            int d = dst[i];
            int pos = atomicAdd(&g_cursor[d], 1);
            g_csrsrc[pos] = src[i];
        }
    } else {
        int i = (b - eb) * 256 + threadIdx.x;   // over n * (F/4)
        if (i < n * (F / 4)) {
            int row = i >> 5;
            float4 v = ((const float4*)feats)[i];
            float s = g_srcnorm[row];
            uint2 o;
            o.x = pack_bf2(v.x * s, v.y * s);
            o.y = pack_bf2(v.z * s, v.w * s);
            ((uint2*)g_h0)[i] = o;
        }
    }
}

// ---------------- fused conv layer: gather-SpMM + bf16 MMA + relu + src_norm fold ----
// dynamic TILE scheduling (one gmem atomic per tile); static node assignment inside tile.
__global__ void __launch_bounds__(256, 5) k_layer128(
    const unsigned* __restrict__ xs,      // bf16-packed, row stride F/2 uints
    const float* __restrict__ W,          // [F][F] row-major fp32
    const float* __restrict__ bias,
    unsigned* __restrict__ out,           // bf16-packed output
    int n, int numTiles, int slot)
{
    __shared__ unsigned shWb[F * AP];     // 34816 B
    __shared__ unsigned shAb[16 * AP];    // 4352 B
    __shared__ float    shB[F];
    __shared__ int      sh_t;

    int tid = threadIdx.x;
    for (int i = tid; i < F * (F / 2); i += 256) {
        int k2 = i >> 7, nn = i & (F - 1);
        shWb[nn * AP + k2] = pack_bf2(W[(2 * k2) * F + nn], W[(2 * k2 + 1) * F + nn]);
    }
    if (tid < F / 4) ((float4*)shB)[tid] = ((const float4*)bias)[tid];

    int w = tid >> 5, lane = tid & 31;
    int g = lane >> 2, tig = lane & 3;

    while (true) {
        if (tid == 0) sh_t = atomicAdd(&g_pre[OFF_TCTR + slot], 1);
        __syncthreads();
        int t = sh_t;
        if (t >= numTiles) break;
        int base = t * 16;

        // --- aggregation: warp handles local nodes w and w+8; lane covers 4 k-cols ---
        #pragma unroll
        for (int s2 = 0; s2 < 2; s2++) {
            int ml = w + s2 * 8;
            int m = base + ml;
            float4 acc = make_float4(0.f, 0.f, 0.f, 0.f);
            if (m < n) {
                int e = g_offsets[m], end = g_offsets[m + 1];
                const unsigned* xb = xs + lane * 2;
                for (; e + 8 <= end; e += 8) {
                    uint2 u[8];
                    #pragma unroll
                    for (int q = 0; q < 8; q++) {
                        int idx = g_csrsrc[e + q];
                        u[q] = *(const uint2*)(xb + (size_t)idx * (F / 2));
                    }
                    #pragma unroll
                    for (int q = 0; q < 8; q++) {
                        acc.x += BF_LO(u[q].x); acc.y += BF_HI(u[q].x);
                        acc.z += BF_LO(u[q].y); acc.w += BF_HI(u[q].y);
                    }
                }
                for (; e + 4 <= end; e += 4) {
                    uint2 u[4];
                    #pragma unroll
                    for (int q = 0; q < 4; q++) {
                        int idx = g_csrsrc[e + q];
                        u[q] = *(const uint2*)(xb + (size_t)idx * (F / 2));
                    }
                    #pragma unroll
                    for (int q = 0; q < 4; q++) {
                        acc.x += BF_LO(u[q].x); acc.y += BF_HI(u[q].x);
                        acc.z += BF_LO(u[q].y); acc.w += BF_HI(u[q].y);
                    }
                }
                for (; e < end; e++) {
                    uint2 u0 = *(const uint2*)(xb + (size_t)g_csrsrc[e] * (F / 2));
                    acc.x += BF_LO(u0.x); acc.y += BF_HI(u0.x);
                    acc.z += BF_LO(u0.y); acc.w += BF_HI(u0.y);
                }
                float dn = g_dstnorm[m];
                acc.x *= dn; acc.y *= dn; acc.z *= dn; acc.w *= dn;
            }
            shAb[ml * AP + lane * 2]     = pack_bf2(acc.x, acc.y);
            shAb[ml * AP + lane * 2 + 1] = pack_bf2(acc.z, acc.w);
        }
        __syncthreads();

        // --- GEMM: warp w owns cols [16w, 16w+16) ---
        int nb0 = w * 16, nb1 = nb0 + 8;
        float2 bb0 = *(float2*)(shB + nb0 + 2 * tig);
        float2 bb1 = *(float2*)(shB + nb1 + 2 * tig);
        float c00 = bb0.x, c01 = bb0.y, c02 = bb0.x, c03 = bb0.y;
        float c10 = bb1.x, c11 = bb1.y, c12 = bb1.x, c13 = bb1.y;

        const unsigned* A0 = shAb + g * AP;
        const unsigned* A1 = shAb + (g + 8) * AP;
        const unsigned* B0 = shWb + (nb0 + g) * AP;
        const unsigned* B1 = shWb + (nb1 + g) * AP;
        #pragma unroll
        for (int kt = 0; kt < 8; kt++) {
            int j0 = kt * 8;
            unsigned a0 = A0[j0 + tig],     a1 = A1[j0 + tig];
            unsigned a2 = A0[j0 + 4 + tig], a3 = A1[j0 + 4 + tig];
            mma_bf16(c00, c01, c02, c03, a0, a1, a2, a3, B0[j0 + tig], B0[j0 + 4 + tig]);
            mma_bf16(c10, c11, c12, c13, a0, a1, a2, a3, B1[j0 + tig], B1[j0 + 4 + tig]);
        }

        int m0 = base + g, m1 = base + g + 8;
        if (m0 < n) {
            float sn = g_srcnorm[m0];
            unsigned* o = out + (size_t)m0 * (F / 2);
            o[nb0 / 2 + tig] = pack_bf2(fmaxf(c00, 0.f) * sn, fmaxf(c01, 0.f) * sn);
            o[nb1 / 2 + tig] = pack_bf2(fmaxf(c10, 0.f) * sn, fmaxf(c11, 0.f) * sn);
        }
        if (m1 < n) {
            float sn = g_srcnorm[m1];
            unsigned* o = out + (size_t)m1 * (F / 2);
            o[nb0 / 2 + tig] = pack_bf2(fmaxf(c02, 0.f) * sn, fmaxf(c03, 0.f) * sn);
            o[nb1 / 2 + tig] = pack_bf2(fmaxf(c12, 0.f) * sn, fmaxf(c13, 0.f) * sn);
        }
        __syncthreads();
    }
}

// ---------------- y = x2s @ W3 via bf16 MMA (dynamic tiles) ----------------
__global__ void __launch_bounds__(256) k_pre3(
    const unsigned* __restrict__ x,       // bf16-packed, row stride 64 uints
    const float* __restrict__ W3,         // [F][64] row-major fp32
    unsigned* __restrict__ y, int n, int numTiles, int slot)
{
    __shared__ unsigned shWb[64 * AP];
    __shared__ unsigned shXb[16 * AP];
    __shared__ int sh_t;
    int tid = threadIdx.x;
    for (int i = tid; i < 64 * (F / 2); i += 256) {
        int k2 = i >> 6, nn = i & 63;
        shWb[nn * AP + k2] = pack_bf2(W3[(2 * k2) * 64 + nn], W3[(2 * k2 + 1) * 64 + nn]);
    }

    int w = tid >> 5, lane = tid & 31;
    int g = lane >> 2, tig = lane & 3;

    while (true) {
        if (tid == 0) sh_t = atomicAdd(&g_pre[OFF_TCTR + slot], 1);
        __syncthreads();
        int t = sh_t;
        if (t >= numTiles) break;
        int base = t * 16;
        {
            int r = tid >> 4, q = tid & 15;
            int node = base + r;
            uint4 v = (node < n) ? ((const uint4*)(x + (size_t)node * 64))[q]
                                 : make_uint4(0u, 0u, 0u, 0u);
            unsigned* p = shXb + r * AP + q * 4;
            p[0] = v.x; p[1] = v.y; p[2] = v.z; p[3] = v.w;
        }
        __syncthreads();

        int nb = w * 8;
        float c0 = 0.f, c1 = 0.f, c2 = 0.f, c3 = 0.f;
        const unsigned* A0 = shXb + g * AP;
        const unsigned* A1 = shXb + (g + 8) * AP;
        const unsigned* B0 = shWb + (nb + g) * AP;
        #pragma unroll
        for (int kt = 0; kt < 8; kt++) {
            int j0 = kt * 8;
            mma_bf16(c0, c1, c2, c3,
                     A0[j0 + tig], A1[j0 + tig], A0[j0 + 4 + tig], A1[j0 + 4 + tig],
                     B0[j0 + tig], B0[j0 + 4 + tig]);
        }
        int m0 = base + g, m1 = base + g + 8;
        if (m0 < n) y[(size_t)m0 * 32 + nb / 2 + tig] = pack_bf2(c0, c1);
        if (m1 < n) y[(size_t)m1 * 32 + nb / 2 + tig] = pack_bf2(c2, c3);
        __syncthreads();
    }
}

// ---------------- layer 3 aggregation (bf16, width 64) + bias + relu + head + sigmoid ------
__global__ void k_layer3(
    const unsigned* __restrict__ y, const float* __restrict__ b3,
    const float* __restrict__ Wp, const float* __restrict__ bp,
    float* __restrict__ out, int n)
{
    int gw = (blockIdx.x * blockDim.x + threadIdx.x) >> 5;
    int lane = threadIdx.x & 31;
    if (gw >= n) return;
    int m = gw;
    int e = g_offsets[m], end = g_offsets[m + 1];
    float2 acc = make_float2(0.f, 0.f);
    const unsigned* yb = y + lane;
    for (; e + 8 <= end; e += 8) {
        unsigned u[8];
        #pragma unroll
        for (int q = 0; q < 8; q++) u[q] = yb[(size_t)g_csrsrc[e + q] * 32];
        #pragma unroll
        for (int q = 0; q < 8; q++) { acc.x += BF_LO(u[q]); acc.y += BF_HI(u[q]); }
    }
    for (; e + 4 <= end; e += 4) {
        unsigned u[4];
        #pragma unroll
        for (int q = 0; q < 4; q++) u[q] = yb[(size_t)g_csrsrc[e + q] * 32];
        #pragma unroll
        for (int q = 0; q < 4; q++) { acc.x += BF_LO(u[q]); acc.y += BF_HI(u[q]); }
    }
    for (; e < end; e++) {
        unsigned u0 = yb[(size_t)g_csrsrc[e] * 32];
        acc.x += BF_LO(u0); acc.y += BF_HI(u0);
    }
    float dn = g_dstnorm[m];
    float2 bb = *(const float2*)(b3 + lane * 2);
    float hx = fmaxf(acc.x * dn + bb.x, 0.f);
    float hy = fmaxf(acc.y * dn + bb.y, 0.f);
    float2 wp = *(const float2*)(Wp + lane * 2);
    float p = hx * wp.x + hy * wp.y;
    #pragma unroll
    for (int o = 16; o; o >>= 1) p += __shfl_xor_sync(0xffffffffu, p, o);
    if (lane == 0) {
        float l = p + bp[0];
        out[m] = 1.f / (1.f + __expf(-l));
    }
}

// ---------------- launch ----------------
extern "C" void kernel_launch(void* const* d_in, const int* in_sizes, int n_in,
                              void* d_out, int out_size)
{
    const float* feats = (const float*)d_in[0];
    const int*   src   = (const int*)d_in[1];
    const int*   dst   = (const int*)d_in[2];
    // d_in[3] = edge_types (unused)
    const float* W1 = (const float*)d_in[4];
    const float* b1 = (const float*)d_in[5];
    const float* W2 = (const float*)d_in[6];
    const float* b2 = (const float*)d_in[7];
    const float* W3 = (const float*)d_in[8];
    const float* b3 = (const float*)d_in[9];
    const float* Wp = (const float*)d_in[10];
    const float* bp = (const float*)d_in[11];
    float* out = (float*)d_out;

    int n = in_sizes[0] / F;   // 50000
    int e = in_sizes[1];       // 800000

    unsigned *h0, *h1, *hy;
    int* prep;
    cudaGetSymbolAddress((void**)&h0, g_h0);
    cudaGetSymbolAddress((void**)&h1, g_h1);
    cudaGetSymbolAddress((void**)&hy, g_hy);
    cudaGetSymbolAddress((void**)&prep, g_pre);

    int nb = (n + 1023) / 1024;
    int tiles = (n + 15) / 16;
    int eb = (e + 255) / 256;
    int sb = (n * (F / 4) + 255) / 256;

    cudaMemsetAsync(prep, 0, sizeof(int) * PRE_INTS);
    k_deg          <<<(e + 255) / 256, 256>>>(src, dst, e);
    k_scan1        <<<nb, 1024>>>(n);
    k_scan2        <<<1, 32>>>(nb);
    k_scan3        <<<(n + 255) / 256, 256>>>(n, e);
    k_scatter_scale<<<eb + sb, 256>>>(src, dst, feats, e, n, eb);

    k_layer128<<<740, 256>>>(h0, W1, b1, h1, n, tiles, 0);
    k_layer128<<<740, 256>>>(h1, W2, b2, h0, n, tiles, 1);
    k_pre3    <<<1184, 256>>>(h0, W3, hy, n, tiles, 2);
    k_layer3  <<<(n * 32 + 255) / 256, 256>>>(hy, b3, Wp, bp, out, n);
}

// round 10
// speedup vs baseline: 1.4109x; 1.0073x over previous
#include <cuda_runtime.h>
#include <math.h>

#define NN 50000
#define NE 800000
#define F  128
#define AP 68   // padded row stride (uints) for bf16x2 smem tiles: conflict-free fragments

// ---- zeroed-by-memset scratch block ----
#define OFF_DEGOUT 0
#define OFF_DEGIN  NN
#define PRE_INTS   (2 * NN)
__device__ int g_pre[PRE_INTS];

__device__ __align__(16) float g_srcnorm[NN];
__device__ __align__(16) float g_dstnorm[NN];
__device__ int   g_offsets[NN + 1];
__device__ int   g_cursor[NN];
__device__ int   g_csrsrc[NE];
__device__ int   g_blksums[64];
__device__ int   g_blkoffs[64];
// bf16-packed feature buffers (2 vals per uint)
__device__ __align__(16) unsigned g_h0[(size_t)NN * F / 2];
__device__ __align__(16) unsigned g_h1[(size_t)NN * F / 2];
__device__ __align__(16) unsigned g_hy[(size_t)NN * 64 / 2];

// ---------------- helpers ----------------
__device__ __forceinline__ unsigned pack_bf2(float lo, float hi) {
    unsigned r;
    asm("cvt.rn.bf16x2.f32 %0, %1, %2;" : "=r"(r) : "f"(hi), "f"(lo));
    return r;
}
#define BF_LO(u) __uint_as_float((u) << 16)
#define BF_HI(u) __uint_as_float((u) & 0xffff0000u)

__device__ __forceinline__ void mma_bf16(
    float& c0, float& c1, float& c2, float& c3,
    unsigned a0, unsigned a1, unsigned a2, unsigned a3,
    unsigned b0, unsigned b1)
{
    asm("mma.sync.aligned.m16n8k16.row.col.f32.bf16.bf16.f32 "
        "{%0,%1,%2,%3},{%4,%5,%6,%7},{%8,%9},{%0,%1,%2,%3};"
        : "+f"(c0), "+f"(c1), "+f"(c2), "+f"(c3)
        : "r"(a0), "r"(a1), "r"(a2), "r"(a3), "r"(b0), "r"(b1));
}

__device__ __forceinline__ int warp_incl_scan(int s, int lane) {
    #pragma unroll
    for (int o = 1; o < 32; o <<= 1) {
        int t = __shfl_up_sync(0xffffffffu, s, o);
        if (lane >= o) s += t;
    }
    return s;
}

#define ACC8(u4) do { \
    a0 += BF_LO((u4).x); a1 += BF_HI((u4).x); \
    a2 += BF_LO((u4).y); a3 += BF_HI((u4).y); \
    a4 += BF_LO((u4).z); a5 += BF_HI((u4).z); \
    a6 += BF_LO((u4).w); a7 += BF_HI((u4).w); } while (0)

// ---------------- preprocessing (proven 5-kernel chain, no spin barriers) ----------------
__global__ void k_deg(const int* __restrict__ src, const int* __restrict__ dst, int e) {
    int i = blockIdx.x * blockDim.x + threadIdx.x;
    if (i < e) {
        atomicAdd(&g_pre[OFF_DEGOUT + src[i]], 1);
        atomicAdd(&g_pre[OFF_DEGIN + dst[i]], 1);
    }
}

// per-1024-block exclusive scan of indeg via warp shuffles
__global__ void k_scan1(int n) {
    __shared__ int warpsum[32];
    int tid = threadIdx.x;
    int i = blockIdx.x * 1024 + tid;
    int lane = tid & 31, wid = tid >> 5;
    int v = (i < n) ? g_pre[OFF_DEGIN + i] : 0;
    int s = warp_incl_scan(v, lane);
    if (lane == 31) warpsum[wid] = s;
    __syncthreads();
    if (wid == 0) warpsum[lane] = warp_incl_scan(warpsum[lane], lane);
    __syncthreads();
    int incl = s + (wid > 0 ? warpsum[wid - 1] : 0);
    if (i < n) g_offsets[i] = incl - v;
    if (tid == 1023) g_blksums[blockIdx.x] = incl;
}

// 1-warp scan over block sums (nb <= 64)
__global__ void k_scan2(int nb) {
    int lane = threadIdx.x;
    int acc = 0;
    for (int b = 0; b < nb; b += 32) {
        int v = (b + lane < nb) ? g_blksums[b + lane] : 0;
        int s = warp_incl_scan(v, lane);
        if (b + lane < nb) g_blkoffs[b + lane] = acc + s - v;
        acc += __shfl_sync(0xffffffffu, s, 31);
    }
}

// finish scan + compute norms (fused)
__global__ void k_scan3(int n, int e) {
    int i = blockIdx.x * blockDim.x + threadIdx.x;
    if (i < n) {
        int o = g_offsets[i] + g_blkoffs[i >> 10];
        g_offsets[i] = o;
        g_cursor[i] = o;
        int od = g_pre[OFF_DEGOUT + i];
        int id = g_pre[OFF_DEGIN + i];
        g_srcnorm[i] = od > 0 ? rsqrtf((float)od) : 0.f;
        g_dstnorm[i] = id > 0 ? rsqrtf((float)id) : 0.f;
    }
    if (i == 0) g_offsets[n] = e;
}

// fused: CSR scatter (blocks [0, eb)) + h0 = bf16(features * src_norm) (blocks [eb, ...))
__global__ void k_scatter_scale(
    const int* __restrict__ src, const int* __restrict__ dst,
    const float* __restrict__ feats, int e, int n, int eb)
{
    int b = blockIdx.x;
    if (b < eb) {
        int i = b * 256 + threadIdx.x;
        if (i < e) {
            int d = dst[i];
            int pos = atomicAdd(&g_cursor[d], 1);
            g_csrsrc[pos] = src[i];
        }
    } else {
        int i = (b - eb) * 256 + threadIdx.x;   // over n * (F/4)
        if (i < n * (F / 4)) {
            int row = i >> 5;
            float4 v = ((const float4*)feats)[i];
            float s = g_srcnorm[row];
            uint2 o;
            o.x = pack_bf2(v.x * s, v.y * s);
            o.y = pack_bf2(v.z * s, v.w * s);
            ((uint2*)g_h0)[i] = o;
        }
    }
}

// ---------------- fused conv layer: half-warp uint4 gather + bf16 MMA + relu + fold ----
// lanes 0-15 even edge, 16-31 odd edge; 8 LDG.128 in flight cover 16 edges.
__global__ void __launch_bounds__(256, 4) k_layer128(
    const unsigned* __restrict__ xs,      // bf16-packed, row = 16 uint4
    const float* __restrict__ W,          // [F][F] row-major fp32
    const float* __restrict__ bias,
    unsigned* __restrict__ out,           // bf16-packed output
    int n, int numTiles)
{
    __shared__ unsigned shWb[F * AP];
    __shared__ __align__(16) unsigned shAb[16 * AP];
    __shared__ float    shB[F];

    int tid = threadIdx.x;
    for (int i = tid; i < F * (F / 2); i += 256) {
        int k2 = i >> 7, nn = i & (F - 1);
        shWb[nn * AP + k2] = pack_bf2(W[(2 * k2) * F + nn], W[(2 * k2 + 1) * F + nn]);
    }
    if (tid < F / 4) ((float4*)shB)[tid] = ((const float4*)bias)[tid];
    __syncthreads();

    int w = tid >> 5, lane = tid & 31;
    int g = lane >> 2, tig = lane & 3;
    int half = lane >> 4, hl = lane & 15;
    const uint4* xr = (const uint4*)xs;

    for (int t = blockIdx.x; t < numTiles; t += gridDim.x) {
        int base = t * 16;

        #pragma unroll
        for (int s2 = 0; s2 < 2; s2++) {
            int ml = w + s2 * 8;
            int m = base + ml;
            float a0 = 0.f, a1 = 0.f, a2 = 0.f, a3 = 0.f;
            float a4 = 0.f, a5 = 0.f, a6 = 0.f, a7 = 0.f;
            int e = 0, end = 0;
            if (m < n) { e = g_offsets[m]; end = g_offsets[m + 1]; }
            for (; e + 16 <= end; e += 16) {
                uint4 u[8];
                #pragma unroll
                for (int q = 0; q < 8; q++) {
                    int idx = g_csrsrc[e + 2 * q + half];
                    u[q] = xr[(size_t)idx * 16 + hl];
                }
                #pragma unroll
                for (int q = 0; q < 8; q++) ACC8(u[q]);
            }
            for (; e + 2 <= end; e += 2) {
                int idx = g_csrsrc[e + half];
                uint4 u = xr[(size_t)idx * 16 + hl];
                ACC8(u);
            }
            if (e < end && half == 0) {
                int idx = g_csrsrc[e];
                uint4 u = xr[(size_t)idx * 16 + hl];
                ACC8(u);
            }
            // combine the two halves
            a0 += __shfl_xor_sync(0xffffffffu, a0, 16);
            a1 += __shfl_xor_sync(0xffffffffu, a1, 16);
            a2 += __shfl_xor_sync(0xffffffffu, a2, 16);
            a3 += __shfl_xor_sync(0xffffffffu, a3, 16);
            a4 += __shfl_xor_sync(0xffffffffu, a4, 16);
            a5 += __shfl_xor_sync(0xffffffffu, a5, 16);
            a6 += __shfl_xor_sync(0xffffffffu, a6, 16);
            a7 += __shfl_xor_sync(0xffffffffu, a7, 16);
            float dn = (m < n) ? g_dstnorm[m] : 0.f;
            if (half == 0) {
                unsigned* p = shAb + ml * AP + hl * 4;
                p[0] = pack_bf2(a0 * dn, a1 * dn);
                p[1] = pack_bf2(a2 * dn, a3 * dn);
                p[2] = pack_bf2(a4 * dn, a5 * dn);
                p[3] = pack_bf2(a6 * dn, a7 * dn);
            }
        }
        __syncthreads();

        // --- GEMM: warp w owns cols [16w, 16w+16) ---
        int nb0 = w * 16, nb1 = nb0 + 8;
        float2 bb0 = *(float2*)(shB + nb0 + 2 * tig);
        float2 bb1 = *(float2*)(shB + nb1 + 2 * tig);
        float c00 = bb0.x, c01 = bb0.y, c02 = bb0.x, c03 = bb0.y;
        float c10 = bb1.x, c11 = bb1.y, c12 = bb1.x, c13 = bb1.y;

        const unsigned* A0 = shAb + g * AP;
        const unsigned* A1 = shAb + (g + 8) * AP;
        const unsigned* B0 = shWb + (nb0 + g) * AP;
        const unsigned* B1 = shWb + (nb1 + g) * AP;
        #pragma unroll
        for (int kt = 0; kt < 8; kt++) {
            int j0 = kt * 8;
            unsigned f0 = A0[j0 + tig],     f1 = A1[j0 + tig];
            unsigned f2 = A0[j0 + 4 + tig], f3 = A1[j0 + 4 + tig];
            mma_bf16(c00, c01, c02, c03, f0, f1, f2, f3, B0[j0 + tig], B0[j0 + 4 + tig]);
            mma_bf16(c10, c11, c12, c13, f0, f1, f2, f3, B1[j0 + tig], B1[j0 + 4 + tig]);
        }

        int m0 = base + g, m1 = base + g + 8;
        if (m0 < n) {
            float sn = g_srcnorm[m0];
            unsigned* o = out + (size_t)m0 * (F / 2);
            o[nb0 / 2 + tig] = pack_bf2(fmaxf(c00, 0.f) * sn, fmaxf(c01, 0.f) * sn);
            o[nb1 / 2 + tig] = pack_bf2(fmaxf(c10, 0.f) * sn, fmaxf(c11, 0.f) * sn);
        }
        if (m1 < n) {
            float sn = g_srcnorm[m1];
            unsigned* o = out + (size_t)m1 * (F / 2);
            o[nb0 / 2 + tig] = pack_bf2(fmaxf(c02, 0.f) * sn, fmaxf(c03, 0.f) * sn);
            o[nb1 / 2 + tig] = pack_bf2(fmaxf(c12, 0.f) * sn, fmaxf(c13, 0.f) * sn);
        }
        __syncthreads();
    }
}

// ---------------- y = x2s @ W3 via bf16 MMA (static tiles) ----------------
__global__ void __launch_bounds__(256) k_pre3(
    const unsigned* __restrict__ x,       // bf16-packed, row stride 64 uints
    const float* __restrict__ W3,         // [F][64] row-major fp32
    unsigned* __restrict__ y, int n, int numTiles)
{
    __shared__ unsigned shWb[64 * AP];
    __shared__ unsigned shXb[16 * AP];
    int tid = threadIdx.x;
    for (int i = tid; i < 64 * (F / 2); i += 256) {
        int k2 = i >> 6, nn = i & 63;
        shWb[nn * AP + k2] = pack_bf2(W3[(2 * k2) * 64 + nn], W3[(2 * k2 + 1) * 64 + nn]);
    }
    __syncthreads();

    int w = tid >> 5, lane = tid & 31;
    int g = lane >> 2, tig = lane & 3;

    for (int t = blockIdx.x; t < numTiles; t += gridDim.x) {
        int base = t * 16;
        {
            int r = tid >> 4, q = tid & 15;
            int node = base + r;
            uint4 v = (node < n) ? ((const uint4*)(x + (size_t)node * 64))[q]
                                 : make_uint4(0u, 0u, 0u, 0u);
            unsigned* p = shXb + r * AP + q * 4;
            p[0] = v.x; p[1] = v.y; p[2] = v.z; p[3] = v.w;
        }
        __syncthreads();

        int nb = w * 8;
        float c0 = 0.f, c1 = 0.f, c2 = 0.f, c3 = 0.f;
        const unsigned* A0 = shXb + g * AP;
        const unsigned* A1 = shXb + (g + 8) * AP;
        const unsigned* B0 = shWb + (nb + g) * AP;
        #pragma unroll
        for (int kt = 0; kt < 8; kt++) {
            int j0 = kt * 8;
            mma_bf16(c0, c1, c2, c3,
                     A0[j0 + tig], A1[j0 + tig], A0[j0 + 4 + tig], A1[j0 + 4 + tig],
                     B0[j0 + tig], B0[j0 + 4 + tig]);
        }
        int m0 = base + g, m1 = base + g + 8;
        if (m0 < n) y[(size_t)m0 * 32 + nb / 2 + tig] = pack_bf2(c0, c1);
        if (m1 < n) y[(size_t)m1 * 32 + nb / 2 + tig] = pack_bf2(c2, c3);
        __syncthreads();
    }
}

// ---------------- layer 3: quarter-warp uint4 gather + bias/relu/head/sigmoid ----------------
__global__ void __launch_bounds__(256) k_layer3(
    const unsigned* __restrict__ y, const float* __restrict__ b3,
    const float* __restrict__ Wp, const float* __restrict__ bp,
    float* __restrict__ out, int n)
{
    int gw = (blockIdx.x * blockDim.x + threadIdx.x) >> 5;   // warp per node
    int lane = threadIdx.x & 31;
    if (gw >= n) return;
    int sub = lane >> 3, ql = lane & 7;   // 4 edge slots x 8 lanes (uint4 each = 8 cols)
    int e = g_offsets[gw], end = g_offsets[gw + 1];
    const uint4* yr = (const uint4*)y;    // row = 8 uint4
    float a0 = 0.f, a1 = 0.f, a2 = 0.f, a3 = 0.f;
    float a4 = 0.f, a5 = 0.f, a6 = 0.f, a7 = 0.f;

    for (; e + 32 <= end; e += 32) {
        uint4 u[8];
        #pragma unroll
        for (int q = 0; q < 8; q++) {
            int idx = g_csrsrc[e + 4 * q + sub];
            u[q] = yr[(size_t)idx * 8 + ql];
        }
        #pragma unroll
        for (int q = 0; q < 8; q++) ACC8(u[q]);
    }
    for (; e + 4 <= end; e += 4) {
        int idx = g_csrsrc[e + sub];
        uint4 u = yr[(size_t)idx * 8 + ql];
        ACC8(u);
    }
    int r = end - e;
    if (sub < r) {
        int idx = g_csrsrc[e + sub];
        uint4 u = yr[(size_t)idx * 8 + ql];
        ACC8(u);
    }
    // reduce over the 4 edge slots (xor 8, 16)
    #pragma unroll
    for (int o = 8; o <= 16; o <<= 1) {
        a0 += __shfl_xor_sync(0xffffffffu, a0, o);
        a1 += __shfl_xor_sync(0xffffffffu, a1, o);
        a2 += __shfl_xor_sync(0xffffffffu, a2, o);
        a3 += __shfl_xor_sync(0xffffffffu, a3, o);
        a4 += __shfl_xor_sync(0xffffffffu, a4, o);
        a5 += __shfl_xor_sync(0xffffffffu, a5, o);
        a6 += __shfl_xor_sync(0xffffffffu, a6, o);
        a7 += __shfl_xor_sync(0xffffffffu, a7, o);
    }
    float dn = g_dstnorm[gw];
    float4 ba = *(const float4*)(b3 + ql * 8);
    float4 bb = *(const float4*)(b3 + ql * 8 + 4);
    float4 wa = *(const float4*)(Wp + ql * 8);
    float4 wb = *(const float4*)(Wp + ql * 8 + 4);
    float p = fmaxf(a0 * dn + ba.x, 0.f) * wa.x + fmaxf(a1 * dn + ba.y, 0.f) * wa.y
            + fmaxf(a2 * dn + ba.z, 0.f) * wa.z + fmaxf(a3 * dn + ba.w, 0.f) * wa.w
            + fmaxf(a4 * dn + bb.x, 0.f) * wb.x + fmaxf(a5 * dn + bb.y, 0.f) * wb.y
            + fmaxf(a6 * dn + bb.z, 0.f) * wb.z + fmaxf(a7 * dn + bb.w, 0.f) * wb.w;
    p += __shfl_xor_sync(0xffffffffu, p, 1);
    p += __shfl_xor_sync(0xffffffffu, p, 2);
    p += __shfl_xor_sync(0xffffffffu, p, 4);
    if (lane == 0) {
        float l = p + bp[0];
        out[gw] = 1.f / (1.f + __expf(-l));
    }
}

// ---------------- launch ----------------
extern "C" void kernel_launch(void* const* d_in, const int* in_sizes, int n_in,
                              void* d_out, int out_size)
{
    const float* feats = (const float*)d_in[0];
    const int*   src   = (const int*)d_in[1];
    const int*   dst   = (const int*)d_in[2];
    // d_in[3] = edge_types (unused)
    const float* W1 = (const float*)d_in[4];
    const float* b1 = (const float*)d_in[5];
    const float* W2 = (const float*)d_in[6];
    const float* b2 = (const float*)d_in[7];
    const float* W3 = (const float*)d_in[8];
    const float* b3 = (const float*)d_in[9];
    const float* Wp = (const float*)d_in[10];
    const float* bp = (const float*)d_in[11];
    float* out = (float*)d_out;

    int n = in_sizes[0] / F;   // 50000
    int e = in_sizes[1];       // 800000

    unsigned *h0, *h1, *hy;
    int* prep;
    cudaGetSymbolAddress((void**)&h0, g_h0);
    cudaGetSymbolAddress((void**)&h1, g_h1);
    cudaGetSymbolAddress((void**)&hy, g_hy);
    cudaGetSymbolAddress((void**)&prep, g_pre);

    int nb = (n + 1023) / 1024;
    int tiles = (n + 15) / 16;
    int eb = (e + 255) / 256;
    int sb = (n * (F / 4) + 255) / 256;

    cudaMemsetAsync(prep, 0, sizeof(int) * PRE_INTS);
    k_deg          <<<(e + 255) / 256, 256>>>(src, dst, e);
    k_scan1        <<<nb, 1024>>>(n);
    k_scan2        <<<1, 32>>>(nb);
    k_scan3        <<<(n + 255) / 256, 256>>>(n, e);
    k_scatter_scale<<<eb + sb, 256>>>(src, dst, feats, e, n, eb);

    k_layer128<<<592, 256>>>(h0, W1, b1, h1, n, tiles);
    k_layer128<<<592, 256>>>(h1, W2, b2, h0, n, tiles);
    k_pre3    <<<1184, 256>>>(h0, W3, hy, n, tiles);
    k_layer3  <<<(n * 32 + 255) / 256, 256>>>(hy, b3, Wp, bp, out, n);
}